// round 1
// baseline (speedup 1.0000x reference)
#include <cuda_runtime.h>
#include <math.h>

#define DMC 128
#define NLC 4
#define NSC 16
#define EDC 256
#define DTRC 8
#define EPSF 1e-5f
#define BSZ 16
#define NMC 80
#define LLC 500
#define NCC 35
#define MROWS (BSZ*LLC)   // 8000
#define PDIM (DTRC + 2*NSC)  // 40

// ---------------- scratch (device globals; no allocation allowed) ----------------
__device__ float g_x[MROWS*DMC];        // residual stream (b,l,d)
__device__ float g_xz[MROWS*2*EDC];     // in_proj output
__device__ float g_xc[MROWS*EDC];       // conv+silu output (xin)
__device__ float g_dbc[MROWS*PDIM];     // x_proj output
__device__ float g_delta[MROWS*EDC];    // softplus(dt)
__device__ float g_y[MROWS*EDC];        // scan output
__device__ float g_rs[MROWS];           // rmsnorm scales
__device__ float g_mu[MROWS];
__device__ float g_rstd[MROWS];
__device__ float g_pooled[BSZ*DMC];

// ---------------- generic fused tiled GEMM: C[m][n] = sum_k A[m][k]*B[n][k] ------
// AMODE: 0 plain, 1 rmsnorm (A*rs[m]*nw[k]), 2 gated (A * silu(z[m,k])), 3 stem gather
// EPI:   0 plain store, 1 conv-bias + BN + silu, 2 residual add into C
#define TBM 64
#define TBN 64
#define TBK 64

template<int AMODE, int EPI>
__global__ void __launch_bounds__(256) gemm_k(
    const float* __restrict__ A, const float* __restrict__ Bw,
    float* __restrict__ C, int N, int Ktot, int lda, int ldb, int ldc,
    const float* __restrict__ p0, const float* __restrict__ p1,
    const float* __restrict__ p2, const float* __restrict__ p3,
    const float* __restrict__ p4, const float* __restrict__ p5,
    const float* __restrict__ p6)
{
    __shared__ float As[TBK][TBM+4];
    __shared__ float Bs[TBK][TBN+4];
    const int m0 = blockIdx.x*TBM, n0 = blockIdx.y*TBN;
    const int tid = threadIdx.x;
    const int tr = tid >> 4, tc = tid & 15;
    float acc[4][4] = {};

    for (int k0 = 0; k0 < Ktot; k0 += TBK) {
        #pragma unroll
        for (int i = 0; i < 16; i++) {
            int flat = i*256 + tid;
            int mo = flat >> 6, ko = flat & 63;
            int kk = k0 + ko;
            int m = m0 + mo;
            float va = 0.f;
            if (kk < Ktot) {
                if (AMODE == 0) {
                    va = A[m*lda + kk];
                } else if (AMODE == 1) {
                    va = A[m*lda + kk] * p0[m] * p1[kk];
                } else if (AMODE == 2) {
                    float z = p0[m*(2*EDC) + EDC + kk];
                    va = A[m*lda + kk] * (z / (1.f + __expf(-z)));
                } else { // stem gather: k = c*5 + kt
                    int c = kk / 5, kt = kk - c*5;
                    int b = m / LLC, l = m - b*LLC;
                    int pos = l - 2 + kt;
                    if (pos >= 0 && pos < LLC) va = p0[(b*NMC + c)*LLC + pos];
                }
            }
            As[ko][mo] = va;
            int n = n0 + mo;
            float vb = 0.f;
            if (kk < Ktot && n < N) vb = Bw[n*ldb + kk];
            Bs[ko][mo] = vb;
        }
        __syncthreads();
        #pragma unroll
        for (int k = 0; k < TBK; k++) {
            float4 a4 = *(const float4*)&As[k][tr*4];
            float4 b4 = *(const float4*)&Bs[k][tc*4];
            float av[4] = {a4.x, a4.y, a4.z, a4.w};
            float bv[4] = {b4.x, b4.y, b4.z, b4.w};
            #pragma unroll
            for (int i = 0; i < 4; i++)
                #pragma unroll
                for (int j = 0; j < 4; j++)
                    acc[i][j] += av[i]*bv[j];
        }
        __syncthreads();
    }

    #pragma unroll
    for (int i = 0; i < 4; i++) {
        int m = m0 + tr*4 + i;
        #pragma unroll
        for (int j = 0; j < 4; j++) {
            int n = n0 + tc*4 + j;
            if (n >= N) continue;
            float v = acc[i][j];
            if (EPI == 1) {
                // v = silu(((v + stem_b) - mean)*rsqrt(var+eps)*gamma + beta)
                v += p2[n];
                v = (v - p3[n]) * rsqrtf(p4[n] + EPSF) * p5[n] + p6[n];
                v = v / (1.f + __expf(-v));
            } else if (EPI == 2) {
                v += C[m*ldc + n];
            }
            C[m*ldc + n] = v;
        }
    }
}

// ---------------- small kernels ----------------
__global__ void rowrms_k(const float* __restrict__ X) {
    int m = blockIdx.x*blockDim.x + threadIdx.x;
    if (m >= MROWS) return;
    const float4* r = (const float4*)(X + m*DMC);
    float s = 0.f;
    #pragma unroll
    for (int i = 0; i < DMC/4; i++) {
        float4 v = r[i];
        s += v.x*v.x + v.y*v.y + v.z*v.z + v.w*v.w;
    }
    g_rs[m] = rsqrtf(s * (1.f/DMC) + EPSF);
}

__global__ void dwconv_k(const float* __restrict__ cw, const float* __restrict__ cb) {
    int m = blockIdx.x; int e = threadIdx.x;
    int b = m / LLC, l = m - b*LLC;
    float acc = cb[e];
    #pragma unroll
    for (int k = 0; k < 4; k++) {
        int l2 = l - 3 + k;
        if (l2 >= 0) acc += g_xz[(b*LLC + l2)*(2*EDC) + e] * cw[e*4 + k];
    }
    g_xc[m*EDC + e] = acc / (1.f + __expf(-acc));
}

__global__ void dtproj_k(const float* __restrict__ dtW, const float* __restrict__ dtb) {
    int m = blockIdx.x; int e = threadIdx.x;
    const float* dr = g_dbc + m*PDIM;
    float acc = dtb[e];
    #pragma unroll
    for (int r = 0; r < DTRC; r++) acc += dr[r]*dtW[e*DTRC + r];
    float sp = (acc > 20.f) ? acc : log1pf(expf(acc));
    g_delta[m*EDC + e] = sp;
}

__global__ void scan_k(const float* __restrict__ Alog, const float* __restrict__ Dp) {
    int b = blockIdx.x;
    int e = blockIdx.y*32 + threadIdx.x;
    float a0 = -expf(Alog[e*NSC]);
    bool ok = true;
    #pragma unroll
    for (int n = 0; n < NSC; n++) {
        float an = -expf(Alog[e*NSC + n]);
        if (fabsf(an - a0*(float)(n+1)) > 1e-4f*fmaxf(1.f, fabsf(an))) ok = false;
    }
    float Dv = Dp[e];
    float h[NSC];
    #pragma unroll
    for (int n = 0; n < NSC; n++) h[n] = 0.f;
    const float* dl  = g_delta + (b*LLC)*EDC + e;
    const float* xcp = g_xc    + (b*LLC)*EDC + e;
    const float* dbc = g_dbc   + (b*LLC)*PDIM;
    float* yo = g_y + (b*LLC)*EDC + e;

    if (ok) {
        for (int l = 0; l < LLC; l++) {
            float d  = dl[l*EDC];
            float xv = xcp[l*EDC];
            float t  = __expf(d * a0);
            float tp = 1.f, ys = 0.f;
            const float* row = dbc + l*PDIM;
            #pragma unroll
            for (int n = 0; n < NSC; n++) {
                tp *= t;                      // t^(n+1) == exp(d*A_n)
                float bx = d * row[DTRC + n] * xv;
                h[n] = tp*h[n] + bx;
                ys += h[n] * row[DTRC + NSC + n];
            }
            yo[l*EDC] = ys + Dv*xv;
        }
    } else {
        float an[NSC];
        #pragma unroll
        for (int n = 0; n < NSC; n++) an[n] = -expf(Alog[e*NSC + n]);
        for (int l = 0; l < LLC; l++) {
            float d  = dl[l*EDC];
            float xv = xcp[l*EDC];
            float ys = 0.f;
            const float* row = dbc + l*PDIM;
            #pragma unroll
            for (int n = 0; n < NSC; n++) {
                float dA = __expf(d * an[n]);
                float bx = d * row[DTRC + n] * xv;
                h[n] = dA*h[n] + bx;
                ys += h[n] * row[DTRC + NSC + n];
            }
            yo[l*EDC] = ys + Dv*xv;
        }
    }
}

__global__ void lnstats_k() {
    int m = blockIdx.x*blockDim.x + threadIdx.x;
    if (m >= MROWS) return;
    const float4* r = (const float4*)(g_x + m*DMC);
    float s = 0.f, s2 = 0.f;
    #pragma unroll
    for (int i = 0; i < DMC/4; i++) {
        float4 v = r[i];
        s  += v.x + v.y + v.z + v.w;
        s2 += v.x*v.x + v.y*v.y + v.z*v.z + v.w*v.w;
    }
    float mu = s * (1.f/DMC);
    float var = s2 * (1.f/DMC) - mu*mu;
    g_mu[m] = mu;
    g_rstd[m] = rsqrtf(var + EPSF);
}

__global__ void pool_k(const float* __restrict__ lw, const float* __restrict__ lb) {
    int idx = blockIdx.x*blockDim.x + threadIdx.x;
    if (idx >= BSZ*DMC) return;
    int b = idx >> 7, d = idx & 127;
    float s = 0.f;
    for (int l = 0; l < LLC; l++) {
        int m = b*LLC + l;
        s += (g_x[m*DMC + d] - g_mu[m]) * g_rstd[m];
    }
    g_pooled[idx] = s * (1.f/LLC) * lw[d] + lb[d];
}

__global__ void head_k(const float* __restrict__ eW, const float* __restrict__ eb,
                       const float* __restrict__ cW, const float* __restrict__ cb,
                       const float* __restrict__ wW, const float* __restrict__ wb,
                       float* __restrict__ out) {
    __shared__ float ps[DMC], es[DMC];
    int b = blockIdx.x, t = threadIdx.x;
    ps[t] = g_pooled[b*DMC + t];
    __syncthreads();
    float acc = eb[t];
    #pragma unroll 4
    for (int k = 0; k < DMC; k++) acc += ps[k]*eW[t*DMC + k];
    float em = acc / (1.f + expf(-acc));
    es[t] = em;
    out[BSZ*NCC + BSZ + b*DMC + t] = em;   // emb at offset 576
    __syncthreads();
    if (t < NCC) {
        float a = cb[t];
        #pragma unroll 4
        for (int k = 0; k < DMC; k++) a += es[k]*cW[t*DMC + k];
        out[b*NCC + t] = a;                // cmd_logits
    }
    if (t == NCC) {
        float a = wb[0];
        #pragma unroll 4
        for (int k = 0; k < DMC; k++) a += es[k]*wW[k];
        out[BSZ*NCC + b] = a;              // wake_logits at offset 560
    }
}

// ---------------- launch ----------------
extern "C" void kernel_launch(void* const* d_in, const int* in_sizes, int n_in,
                              void* d_out, int out_size) {
    const float* feat    = (const float*)d_in[0];
    const float* stem_w  = (const float*)d_in[1];
    const float* stem_b  = (const float*)d_in[2];
    const float* bn_g    = (const float*)d_in[3];
    const float* bn_b    = (const float*)d_in[4];
    const float* bn_m    = (const float*)d_in[5];
    const float* bn_v    = (const float*)d_in[6];
    const float* norm_w  = (const float*)d_in[7];
    const float* inW     = (const float*)d_in[8];
    const float* convw   = (const float*)d_in[9];
    const float* convb   = (const float*)d_in[10];
    const float* xW      = (const float*)d_in[11];
    const float* dtW     = (const float*)d_in[12];
    const float* dtb     = (const float*)d_in[13];
    const float* Alog    = (const float*)d_in[14];
    const float* Dp      = (const float*)d_in[15];
    const float* oW      = (const float*)d_in[16];
    const float* ln_w    = (const float*)d_in[17];
    const float* ln_b    = (const float*)d_in[18];
    const float* eW      = (const float*)d_in[19];
    const float* eb      = (const float*)d_in[20];
    const float* cW      = (const float*)d_in[21];
    const float* cb      = (const float*)d_in[22];
    const float* wW      = (const float*)d_in[23];
    const float* wb      = (const float*)d_in[24];
    float* out = (float*)d_out;

    static float *px = nullptr, *pxz = nullptr, *pxc = nullptr, *pdbc = nullptr, *py = nullptr;
    static float *prs = nullptr, *pnwdummy = nullptr;
    if (!px) {
        cudaGetSymbolAddress((void**)&px,   g_x);
        cudaGetSymbolAddress((void**)&pxz,  g_xz);
        cudaGetSymbolAddress((void**)&pxc,  g_xc);
        cudaGetSymbolAddress((void**)&pdbc, g_dbc);
        cudaGetSymbolAddress((void**)&py,   g_y);
        cudaGetSymbolAddress((void**)&prs,  g_rs);
        (void)pnwdummy;
    }

    const int MB = MROWS/TBM; // 125

    // stem: M=8000, N=128, K=400 (gathered A), BN+silu epilogue -> g_x
    gemm_k<3,1><<<dim3(MB, DMC/TBN), 256>>>(
        nullptr, stem_w, px, DMC, NMC*5, 0, NMC*5, DMC,
        feat, nullptr, stem_b, bn_m, bn_v, bn_g, bn_b);

    for (int i = 0; i < NLC; i++) {
        const float* nw_i  = norm_w + i*DMC;
        const float* inW_i = inW    + i*(2*EDC)*DMC;
        const float* cw_i  = convw  + i*EDC*4;
        const float* cb_i  = convb  + i*EDC;
        const float* xW_i  = xW     + i*PDIM*EDC;
        const float* dtW_i = dtW    + i*EDC*DTRC;
        const float* dtb_i = dtb    + i*EDC;
        const float* Al_i  = Alog   + i*EDC*NSC;
        const float* D_i   = Dp     + i*EDC;
        const float* oW_i  = oW     + i*DMC*EDC;

        rowrms_k<<<(MROWS+255)/256, 256>>>(px);
        // rmsnorm + in_proj: M=8000, N=512, K=128 -> g_xz
        gemm_k<1,0><<<dim3(MB, (2*EDC)/TBN), 256>>>(
            px, inW_i, pxz, 2*EDC, DMC, DMC, DMC, 2*EDC,
            prs, nw_i, nullptr, nullptr, nullptr, nullptr, nullptr);
        // depthwise causal conv + silu -> g_xc
        dwconv_k<<<MROWS, EDC>>>(cw_i, cb_i);
        // x_proj: M=8000, N=40, K=256 -> g_dbc
        gemm_k<0,0><<<dim3(MB, 1), 256>>>(
            pxc, xW_i, pdbc, PDIM, EDC, EDC, EDC, PDIM,
            nullptr, nullptr, nullptr, nullptr, nullptr, nullptr, nullptr);
        // dt_proj + softplus -> g_delta
        dtproj_k<<<MROWS, EDC>>>(dtW_i, dtb_i);
        // selective scan + C-projection + D skip -> g_y
        scan_k<<<dim3(BSZ, EDC/32), 32>>>(Al_i, D_i);
        // gate + out_proj + residual: M=8000, N=128, K=256, C = g_x (in-place add)
        gemm_k<2,2><<<dim3(MB, DMC/TBN), 256>>>(
            py, oW_i, px, DMC, EDC, EDC, EDC, DMC,
            pxz, nullptr, nullptr, nullptr, nullptr, nullptr, nullptr);
    }

    lnstats_k<<<(MROWS+255)/256, 256>>>();
    pool_k<<<(BSZ*DMC+255)/256, 256>>>(ln_w, ln_b);
    head_k<<<BSZ, DMC>>>(eW, eb, cW, cb, wW, wb, out);
    (void)in_sizes; (void)n_in; (void)out_size;
}

// round 2
// speedup vs baseline: 2.2047x; 2.2047x over previous
#include <cuda_runtime.h>
#include <math.h>

#define DMC 128
#define NLC 4
#define NSC 16
#define EDC 256
#define DTRC 8
#define EPSF 1e-5f
#define BSZ 16
#define NMC 80
#define LLC 500
#define NCC 35
#define MROWS (BSZ*LLC)       // 8000
#define PDIM (DTRC + 2*NSC)   // 40
#define CHUNKS 10
#define CLEN (LLC/CHUNKS)     // 50

// ---------------- scratch (device globals) ----------------
__device__ float g_x[MROWS*DMC];
__device__ float g_xz[MROWS*2*EDC];
__device__ float g_xc[MROWS*EDC];
__device__ float g_dbc[MROWS*PDIM];
__device__ float g_delta[MROWS*EDC];
__device__ float g_y[MROWS*EDC];
__device__ float g_rs[MROWS];
__device__ float g_mu[MROWS];
__device__ float g_rstd[MROWS];
__device__ float g_pooled[BSZ*DMC];
__device__ float g_cA[BSZ*CHUNKS*NSC*EDC];   // layout [b][c][n][e]
__device__ float g_cB[BSZ*CHUNKS*NSC*EDC];
__device__ float g_hin[BSZ*CHUNKS*NSC*EDC];

__device__ __forceinline__ float siluf(float v){ return v / (1.f + __expf(-v)); }

// ---------------- double-buffered tiled GEMM: C[m][n] = sum_k A[m][k]*B[n][k] ----
// AMODE: 0 plain, 1 rmsnorm (A*rs[m]*nw[k]), 2 gated (A*silu(z[m,k])), 3 stem gather
// EPI:   0 plain store, 1 stem-bias+BN+silu, 2 residual add into C
template<int TBM, int TBN, int AMODE, int EPI>
__global__ void __launch_bounds__(256) gemm2(
    const float* __restrict__ A, const float* __restrict__ Bw, float* __restrict__ C,
    int M, int N, int Ktot, int lda, int ldb, int ldc,
    const float* __restrict__ p0, const float* __restrict__ p1,
    const float* __restrict__ p2, const float* __restrict__ p3,
    const float* __restrict__ p4, const float* __restrict__ p5,
    const float* __restrict__ p6)
{
    constexpr int TBK = 16;
    constexpr int TM = TBM/16, TN = TBN/16;
    constexpr int LA = TBM/64;
    constexpr int LB = TBN/64;
    __shared__ __align__(16) float As[2][TBK][TBM+4];
    __shared__ __align__(16) float Bs[2][TBK][TBN+4];
    const int tid = threadIdx.x;
    const int m0 = blockIdx.x*TBM, n0 = blockIdx.y*TBN;
    const int tr = tid>>4, tc = tid&15;

    float4 ra[LA]; float4 rb[LB];
    float acc[TM][TN] = {};

    auto ldg = [&](int k0){
        #pragma unroll
        for (int i=0;i<LA;i++){
            int idx = i*256 + tid;
            int mo = idx>>2, kq = idx&3;
            int m = m0+mo, k = k0 + kq*4;
            float4 v = make_float4(0.f,0.f,0.f,0.f);
            if (AMODE==3) {
                if (m < M) {
                    int b = m / LLC, l = m - b*LLC;
                    float t[4];
                    #pragma unroll
                    for (int j=0;j<4;j++){
                        int kk = k+j; int c = kk/5, kt = kk - c*5;
                        int pos = l - 2 + kt;
                        t[j] = (pos>=0 && pos<LLC) ? p0[(b*NMC+c)*LLC+pos] : 0.f;
                    }
                    v = make_float4(t[0],t[1],t[2],t[3]);
                }
            } else if (m < M) {
                v = *(const float4*)&A[m*lda + k];
                if (AMODE==1) {
                    float s = p0[m];
                    float4 w = *(const float4*)&p1[k];
                    v.x *= s*w.x; v.y *= s*w.y; v.z *= s*w.z; v.w *= s*w.w;
                } else if (AMODE==2) {
                    float4 z = *(const float4*)&p0[m*(2*EDC)+EDC+k];
                    v.x *= siluf(z.x); v.y *= siluf(z.y);
                    v.z *= siluf(z.z); v.w *= siluf(z.w);
                }
            }
            ra[i]=v;
        }
        #pragma unroll
        for (int i=0;i<LB;i++){
            int idx = i*256+tid;
            int no = idx>>2, kq = idx&3;
            int n = n0+no, k = k0+kq*4;
            float4 v = make_float4(0.f,0.f,0.f,0.f);
            if (n < N) v = *(const float4*)&Bw[n*ldb + k];
            rb[i]=v;
        }
    };
    auto sts = [&](int s){
        #pragma unroll
        for (int i=0;i<LA;i++){
            int idx=i*256+tid; int mo=idx>>2, kq=idx&3;
            As[s][kq*4+0][mo]=ra[i].x; As[s][kq*4+1][mo]=ra[i].y;
            As[s][kq*4+2][mo]=ra[i].z; As[s][kq*4+3][mo]=ra[i].w;
        }
        #pragma unroll
        for (int i=0;i<LB;i++){
            int idx=i*256+tid; int no=idx>>2, kq=idx&3;
            Bs[s][kq*4+0][no]=rb[i].x; Bs[s][kq*4+1][no]=rb[i].y;
            Bs[s][kq*4+2][no]=rb[i].z; Bs[s][kq*4+3][no]=rb[i].w;
        }
    };

    const int nk = Ktot/TBK;
    ldg(0); sts(0); __syncthreads();
    for (int kt=0; kt<nk; kt++){
        int s = kt&1;
        if (kt+1<nk) ldg((kt+1)*TBK);
        #pragma unroll
        for (int k=0;k<TBK;k++){
            float a[TM], b[TN];
            #pragma unroll
            for (int i=0;i<TM/4;i++) *(float4*)&a[i*4] = *(const float4*)&As[s][k][tr*TM + i*4];
            #pragma unroll
            for (int j=0;j<TN/4;j++) *(float4*)&b[j*4] = *(const float4*)&Bs[s][k][tc*TN + j*4];
            #pragma unroll
            for (int i=0;i<TM;i++)
                #pragma unroll
                for (int j=0;j<TN;j++) acc[i][j] += a[i]*b[j];
        }
        if (kt+1<nk){ sts(s^1); __syncthreads(); }
    }

    #pragma unroll
    for (int i=0;i<TM;i++){
        int m = m0 + tr*TM + i;
        if (m >= M) continue;
        #pragma unroll
        for (int jq=0;jq<TN/4;jq++){
            int n = n0 + tc*TN + jq*4;
            if (n >= N) continue;
            float4 v = make_float4(acc[i][jq*4+0],acc[i][jq*4+1],acc[i][jq*4+2],acc[i][jq*4+3]);
            if (EPI==1){
                float* vv=&v.x;
                #pragma unroll
                for (int j=0;j<4;j++){
                    float t = vv[j] + p2[n+j];
                    t = (t - p3[n+j]) * rsqrtf(p4[n+j]+EPSF) * p5[n+j] + p6[n+j];
                    vv[j] = siluf(t);
                }
            } else if (EPI==2){
                float4 c = *(const float4*)&C[m*ldc+n];
                v.x+=c.x; v.y+=c.y; v.z+=c.z; v.w+=c.w;
            }
            *(float4*)&C[m*ldc+n] = v;
        }
    }
}

// ---------------- small kernels ----------------
__global__ void rowrms_k(const float* __restrict__ X) {
    int m = blockIdx.x*blockDim.x + threadIdx.x;
    if (m >= MROWS) return;
    const float4* r = (const float4*)(X + m*DMC);
    float s = 0.f;
    #pragma unroll
    for (int i = 0; i < DMC/4; i++) {
        float4 v = r[i];
        s += v.x*v.x + v.y*v.y + v.z*v.z + v.w*v.w;
    }
    g_rs[m] = rsqrtf(s * (1.f/DMC) + EPSF);
}

__global__ void dwconv_k(const float* __restrict__ cw, const float* __restrict__ cb) {
    int m = blockIdx.x; int e = threadIdx.x;
    int b = m / LLC, l = m - b*LLC;
    float acc = cb[e];
    #pragma unroll
    for (int k = 0; k < 4; k++) {
        int l2 = l - 3 + k;
        if (l2 >= 0) acc += g_xz[(b*LLC + l2)*(2*EDC) + e] * cw[e*4 + k];
    }
    g_xc[m*EDC + e] = siluf(acc);
}

__global__ void dtproj_k(const float* __restrict__ dtW, const float* __restrict__ dtb) {
    int m = blockIdx.x; int e = threadIdx.x;
    const float* dr = g_dbc + m*PDIM;
    float acc = dtb[e];
    #pragma unroll
    for (int r = 0; r < DTRC; r++) acc += dr[r]*dtW[e*DTRC + r];
    float sp = (acc > 20.f) ? acc : log1pf(expf(acc));
    g_delta[m*EDC + e] = sp;
}

// ---------------- chunked selective scan ----------------
// pass1: chunk-local recurrence with h=0; store carry (prodA, h_end)
__global__ void scan_pass1(const float* __restrict__ Alog) {
    int b = blockIdx.x;
    int c = blockIdx.z;
    int e = blockIdx.y*blockDim.x + threadIdx.x;
    float a0 = -expf(Alog[e*NSC]);
    bool ok = true;
    #pragma unroll
    for (int n = 0; n < NSC; n++) {
        float an = -expf(Alog[e*NSC + n]);
        if (fabsf(an - a0*(float)(n+1)) > 1e-4f*fmaxf(1.f, fabsf(an))) ok = false;
    }
    float h[NSC], P[NSC];
    #pragma unroll
    for (int n = 0; n < NSC; n++) { h[n]=0.f; P[n]=1.f; }
    int l0 = c*CLEN;
    const float* dl  = g_delta + (b*LLC+l0)*EDC + e;
    const float* xcp = g_xc    + (b*LLC+l0)*EDC + e;
    const float* dbc = g_dbc   + (b*LLC+l0)*PDIM;

    if (ok) {
        for (int l = 0; l < CLEN; l++) {
            float d  = dl[l*EDC];
            float xv = xcp[l*EDC];
            float dx = d*xv;
            float t  = __expf(d * a0);
            float tp = 1.f;
            const float* row = dbc + l*PDIM;
            #pragma unroll
            for (int n = 0; n < NSC; n++) {
                tp *= t;
                h[n] = tp*h[n] + dx*row[DTRC + n];
                P[n] *= tp;
            }
        }
    } else {
        float an[NSC];
        #pragma unroll
        for (int n = 0; n < NSC; n++) an[n] = -expf(Alog[e*NSC + n]);
        for (int l = 0; l < CLEN; l++) {
            float d  = dl[l*EDC];
            float xv = xcp[l*EDC];
            float dx = d*xv;
            const float* row = dbc + l*PDIM;
            #pragma unroll
            for (int n = 0; n < NSC; n++) {
                float dA = __expf(d * an[n]);
                h[n] = dA*h[n] + dx*row[DTRC + n];
                P[n] *= dA;
            }
        }
    }
    int base = ((b*CHUNKS + c)*NSC)*EDC + e;
    #pragma unroll
    for (int n = 0; n < NSC; n++) {
        g_cA[base + n*EDC] = P[n];
        g_cB[base + n*EDC] = h[n];
    }
}

// pass2: tiny sequential scan over chunk carries
__global__ void scan_pass2() {
    int idx = blockIdx.x*blockDim.x + threadIdx.x;
    if (idx >= BSZ*NSC*EDC) return;
    int b = idx / (NSC*EDC);
    int r = idx - b*(NSC*EDC);
    float hin = 0.f;
    for (int c = 0; c < CHUNKS; c++) {
        int off = (b*CHUNKS + c)*NSC*EDC + r;
        g_hin[off] = hin;
        hin = g_cA[off]*hin + g_cB[off];
    }
}

// pass3: replay with correct h_init, emit y = h·C + D*x
__global__ void scan_pass3(const float* __restrict__ Alog, const float* __restrict__ Dp) {
    int b = blockIdx.x;
    int c = blockIdx.z;
    int e = blockIdx.y*blockDim.x + threadIdx.x;
    float a0 = -expf(Alog[e*NSC]);
    bool ok = true;
    #pragma unroll
    for (int n = 0; n < NSC; n++) {
        float an = -expf(Alog[e*NSC + n]);
        if (fabsf(an - a0*(float)(n+1)) > 1e-4f*fmaxf(1.f, fabsf(an))) ok = false;
    }
    float Dv = Dp[e];
    float h[NSC];
    int base = ((b*CHUNKS + c)*NSC)*EDC + e;
    #pragma unroll
    for (int n = 0; n < NSC; n++) h[n] = g_hin[base + n*EDC];
    int l0 = c*CLEN;
    const float* dl  = g_delta + (b*LLC+l0)*EDC + e;
    const float* xcp = g_xc    + (b*LLC+l0)*EDC + e;
    const float* dbc = g_dbc   + (b*LLC+l0)*PDIM;
    float* yo = g_y + (b*LLC+l0)*EDC + e;

    if (ok) {
        for (int l = 0; l < CLEN; l++) {
            float d  = dl[l*EDC];
            float xv = xcp[l*EDC];
            float dx = d*xv;
            float t  = __expf(d * a0);
            float tp = 1.f, ys = 0.f;
            const float* row = dbc + l*PDIM;
            #pragma unroll
            for (int n = 0; n < NSC; n++) {
                tp *= t;
                h[n] = tp*h[n] + dx*row[DTRC + n];
                ys += h[n] * row[DTRC + NSC + n];
            }
            yo[l*EDC] = ys + Dv*xv;
        }
    } else {
        float an[NSC];
        #pragma unroll
        for (int n = 0; n < NSC; n++) an[n] = -expf(Alog[e*NSC + n]);
        for (int l = 0; l < CLEN; l++) {
            float d  = dl[l*EDC];
            float xv = xcp[l*EDC];
            float dx = d*xv;
            float ys = 0.f;
            const float* row = dbc + l*PDIM;
            #pragma unroll
            for (int n = 0; n < NSC; n++) {
                float dA = __expf(d * an[n]);
                h[n] = dA*h[n] + dx*row[DTRC + n];
                ys += h[n] * row[DTRC + NSC + n];
            }
            yo[l*EDC] = ys + Dv*xv;
        }
    }
}

// ---------------- tail kernels ----------------
__global__ void lnstats_k() {
    int m = blockIdx.x*blockDim.x + threadIdx.x;
    if (m >= MROWS) return;
    const float4* r = (const float4*)(g_x + m*DMC);
    float s = 0.f, s2 = 0.f;
    #pragma unroll
    for (int i = 0; i < DMC/4; i++) {
        float4 v = r[i];
        s  += v.x + v.y + v.z + v.w;
        s2 += v.x*v.x + v.y*v.y + v.z*v.z + v.w*v.w;
    }
    float mu = s * (1.f/DMC);
    float var = s2 * (1.f/DMC) - mu*mu;
    g_mu[m] = mu;
    g_rstd[m] = rsqrtf(var + EPSF);
}

__global__ void pool_k(const float* __restrict__ lw, const float* __restrict__ lb) {
    int idx = blockIdx.x*blockDim.x + threadIdx.x;
    if (idx >= BSZ*DMC) return;
    int b = idx >> 7, d = idx & 127;
    float s = 0.f;
    for (int l = 0; l < LLC; l++) {
        int m = b*LLC + l;
        s += (g_x[m*DMC + d] - g_mu[m]) * g_rstd[m];
    }
    g_pooled[idx] = s * (1.f/LLC) * lw[d] + lb[d];
}

__global__ void head_k(const float* __restrict__ eW, const float* __restrict__ eb,
                       const float* __restrict__ cW, const float* __restrict__ cb,
                       const float* __restrict__ wW, const float* __restrict__ wb,
                       float* __restrict__ out) {
    __shared__ float ps[DMC], es[DMC];
    int b = blockIdx.x, t = threadIdx.x;
    ps[t] = g_pooled[b*DMC + t];
    __syncthreads();
    float acc = eb[t];
    #pragma unroll 4
    for (int k = 0; k < DMC; k++) acc += ps[k]*eW[t*DMC + k];
    float em = acc / (1.f + expf(-acc));
    es[t] = em;
    out[BSZ*NCC + BSZ + b*DMC + t] = em;
    __syncthreads();
    if (t < NCC) {
        float a = cb[t];
        #pragma unroll 4
        for (int k = 0; k < DMC; k++) a += es[k]*cW[t*DMC + k];
        out[b*NCC + t] = a;
    }
    if (t == NCC) {
        float a = wb[0];
        #pragma unroll 4
        for (int k = 0; k < DMC; k++) a += es[k]*wW[k];
        out[BSZ*NCC + b] = a;
    }
}

// ---------------- launch ----------------
extern "C" void kernel_launch(void* const* d_in, const int* in_sizes, int n_in,
                              void* d_out, int out_size) {
    const float* feat    = (const float*)d_in[0];
    const float* stem_w  = (const float*)d_in[1];
    const float* stem_b  = (const float*)d_in[2];
    const float* bn_g    = (const float*)d_in[3];
    const float* bn_b    = (const float*)d_in[4];
    const float* bn_m    = (const float*)d_in[5];
    const float* bn_v    = (const float*)d_in[6];
    const float* norm_w  = (const float*)d_in[7];
    const float* inW     = (const float*)d_in[8];
    const float* convw   = (const float*)d_in[9];
    const float* convb   = (const float*)d_in[10];
    const float* xW      = (const float*)d_in[11];
    const float* dtW     = (const float*)d_in[12];
    const float* dtb     = (const float*)d_in[13];
    const float* Alog    = (const float*)d_in[14];
    const float* Dp      = (const float*)d_in[15];
    const float* oW      = (const float*)d_in[16];
    const float* ln_w    = (const float*)d_in[17];
    const float* ln_b    = (const float*)d_in[18];
    const float* eW      = (const float*)d_in[19];
    const float* eb      = (const float*)d_in[20];
    const float* cW      = (const float*)d_in[21];
    const float* cb      = (const float*)d_in[22];
    const float* wW      = (const float*)d_in[23];
    const float* wb      = (const float*)d_in[24];
    float* out = (float*)d_out;

    static float *px=nullptr, *pxz=nullptr, *pxc=nullptr, *pdbc=nullptr, *py=nullptr, *prs=nullptr;
    if (!px) {
        cudaGetSymbolAddress((void**)&px,   g_x);
        cudaGetSymbolAddress((void**)&pxz,  g_xz);
        cudaGetSymbolAddress((void**)&pxc,  g_xc);
        cudaGetSymbolAddress((void**)&pdbc, g_dbc);
        cudaGetSymbolAddress((void**)&py,   g_y);
        cudaGetSymbolAddress((void**)&prs,  g_rs);
    }

    const int MB128 = (MROWS + 127)/128;   // 63
    const int MB64  = MROWS/64;            // 125

    // stem: M=8000, N=128, K=400 (gathered A) + BN + silu -> g_x
    gemm2<128,64,3,1><<<dim3(MB128, DMC/64), 256>>>(
        nullptr, stem_w, px, MROWS, DMC, NMC*5, 0, NMC*5, DMC,
        feat, nullptr, stem_b, bn_m, bn_v, bn_g, bn_b);

    for (int i = 0; i < NLC; i++) {
        const float* nw_i  = norm_w + i*DMC;
        const float* inW_i = inW    + i*(2*EDC)*DMC;
        const float* cw_i  = convw  + i*EDC*4;
        const float* cb_i  = convb  + i*EDC;
        const float* xW_i  = xW     + i*PDIM*EDC;
        const float* dtW_i = dtW    + i*EDC*DTRC;
        const float* dtb_i = dtb    + i*EDC;
        const float* Al_i  = Alog   + i*EDC*NSC;
        const float* D_i   = Dp     + i*EDC;
        const float* oW_i  = oW     + i*DMC*EDC;

        rowrms_k<<<(MROWS+255)/256, 256>>>(px);
        gemm2<128,64,1,0><<<dim3(MB128, (2*EDC)/64), 256>>>(
            px, inW_i, pxz, MROWS, 2*EDC, DMC, DMC, DMC, 2*EDC,
            prs, nw_i, nullptr, nullptr, nullptr, nullptr, nullptr);
        dwconv_k<<<MROWS, EDC>>>(cw_i, cb_i);
        gemm2<64,64,0,0><<<dim3(MB64, 1), 256>>>(
            pxc, xW_i, pdbc, MROWS, PDIM, EDC, EDC, EDC, PDIM,
            nullptr, nullptr, nullptr, nullptr, nullptr, nullptr, nullptr);
        dtproj_k<<<MROWS, EDC>>>(dtW_i, dtb_i);
        scan_pass1<<<dim3(BSZ, EDC/128, CHUNKS), 128>>>(Al_i);
        scan_pass2<<<(BSZ*NSC*EDC + 255)/256, 256>>>();
        scan_pass3<<<dim3(BSZ, EDC/128, CHUNKS), 128>>>(Al_i, D_i);
        gemm2<128,64,2,2><<<dim3(MB128, DMC/64), 256>>>(
            py, oW_i, px, MROWS, DMC, EDC, EDC, EDC, DMC,
            pxz, nullptr, nullptr, nullptr, nullptr, nullptr, nullptr);
    }

    lnstats_k<<<(MROWS+255)/256, 256>>>();
    pool_k<<<(BSZ*DMC+255)/256, 256>>>(ln_w, ln_b);
    head_k<<<BSZ, DMC>>>(eW, eb, cW, cb, wW, wb, out);
    (void)in_sizes; (void)n_in; (void)out_size;
}